// round 1
// baseline (speedup 1.0000x reference)
#include <cuda_runtime.h>
#include <cstdint>

// Fused FP4(E2M1) weight-only linear:  out[M,N] = inp[M,K] @ W^T + bias
//   W[n,k] = LUT4(nibble) * scales[n, k/16] * amax
// M=32, K=8192, N=8192 expected (derived at runtime; requires M==32, K%256==0, N%256==0)

#define KTILE   256
#define ASTRIDE 36   // padded floats per k-row of the activation tile (16B aligned, bank-staggered)

// Split-K partial buffer: [KC][N][M] fp32, KC = K/KTILE = 32, N=8192, M=32  -> 33.5 MB
__device__ float g_partial[32u * 8192u * 32u];

__device__ __forceinline__ unsigned long long dup2(float w){
    unsigned long long r;
    asm("mov.b64 %0, {%1, %1};" : "=l"(r) : "f"(w));
    return r;
}
__device__ __forceinline__ void fma2(unsigned long long &acc, unsigned long long a, unsigned long long b){
    asm("fma.rn.f32x2 %0, %1, %2, %0;" : "+l"(acc) : "l"(a), "l"(b));
}
__device__ __forceinline__ void unpack2(unsigned long long v, float &lo, float &hi){
    asm("mov.b64 {%0, %1}, %2;" : "=f"(lo), "=f"(hi) : "l"(v));
}

// Decode one packed byte (2 nibbles = weights for k, k+1).
// Magnitudes*4 = {0,2,4,6,8,12,16,24} selected with a single PRMT; s4 already includes scale*amax*0.25.
__device__ __forceinline__ void decode2(unsigned b, float s4, float &w0, float &w1){
    unsigned r = __byte_perm(0x06040200u, 0x18100C08u, b & 0x77u);
    int v0 = (int)(r & 0xFFu);
    int v1 = (int)((r >> 8) & 0xFFu);
    v0 = (b & 0x08u)  ? -v0 : v0;   // sign of low nibble
    v1 = (b & 0x80u)  ? -v1 : v1;   // sign of high nibble
    w0 = (float)v0 * s4;
    w1 = (float)v1 * s4;
}

__global__ void __launch_bounds__(128, 4) gemm_fp4_kernel(
    const float* __restrict__ inp,      // [M=32, K]
    const int*   __restrict__ qw,       // [N, K/2] (one payload byte per int32)
    const float* __restrict__ scales,   // [N, K/16]
    const float* __restrict__ amax,     // [1]
    int N, int K)
{
    __shared__ __align__(16) float aS[KTILE * ASTRIDE];

    const int tid = threadIdx.x;
    const int k0  = blockIdx.y * KTILE;

    // ---- stage activation tile transposed: aS[kk][m] = inp[m][k0+kk], m=0..31 ----
    #pragma unroll
    for (int i = 0; i < 16; ++i){
        int e4 = tid + 128 * i;            // 0..2047 over 32 rows x 64 float4
        int m  = e4 >> 6;
        int kq = e4 & 63;
        const float4 v = *reinterpret_cast<const float4*>(inp + (size_t)m * K + k0 + 4 * kq);
        float* d = aS + (4 * kq) * ASTRIDE + m;
        d[0 * ASTRIDE] = v.x; d[1 * ASTRIDE] = v.y; d[2 * ASTRIDE] = v.z; d[3 * ASTRIDE] = v.w;
    }
    __syncthreads();

    const int warp = tid >> 5, lane = tid & 31;
    const int n0 = blockIdx.x * 256 + warp * 64 + lane;   // row 0 for this lane
    const int n1 = n0 + 32;                               // row 1
    const float amax4 = amax[0] * 0.25f;                  // fold 1/4 from the x4 LUT

    unsigned long long acc0[16], acc1[16];                // f32x2 accumulators: token pairs
    #pragma unroll
    for (int p = 0; p < 16; ++p){ acc0[p] = 0ull; acc1[p] = 0ull; }

    const int kints = K >> 1;
    const int4* q0p = reinterpret_cast<const int4*>(qw + (size_t)n0 * kints + (k0 >> 1));
    const int4* q1p = reinterpret_cast<const int4*>(qw + (size_t)n1 * kints + (k0 >> 1));
    const int ksc = K >> 4;
    const float* s0p = scales + (size_t)n0 * ksc + (k0 >> 4);
    const float* s1p = scales + (size_t)n1 * ksc + (k0 >> 4);

    for (int it = 0; it < KTILE / 16; ++it){              // 16 k per iteration (one scale block)
        const float s4_0 = __ldg(s0p + it) * amax4;
        const float s4_1 = __ldg(s1p + it) * amax4;
        #pragma unroll
        for (int h = 0; h < 2; ++h){                      // 8 k per int4 load
            const int4 qa = __ldg(q0p + 2 * it + h);
            const int4 qb = __ldg(q1p + 2 * it + h);
            const unsigned qaU[4] = {(unsigned)qa.x,(unsigned)qa.y,(unsigned)qa.z,(unsigned)qa.w};
            const unsigned qbU[4] = {(unsigned)qb.x,(unsigned)qb.y,(unsigned)qb.z,(unsigned)qb.w};
            #pragma unroll
            for (int j = 0; j < 4; ++j){                  // one byte = k-pair per row
                float w00, w01, w10, w11;
                decode2(qaU[j], s4_0, w00, w01);
                decode2(qbU[j], s4_1, w10, w11);
                const unsigned long long b00 = dup2(w00), b01 = dup2(w01);
                const unsigned long long b10 = dup2(w10), b11 = dup2(w11);
                const int k = it * 16 + h * 8 + 2 * j;
                const ulonglong2* ae = reinterpret_cast<const ulonglong2*>(aS + (size_t)k       * ASTRIDE);
                const ulonglong2* ao = reinterpret_cast<const ulonglong2*>(aS + (size_t)(k + 1) * ASTRIDE);
                #pragma unroll
                for (int qn = 0; qn < 8; ++qn){           // even k: 16 token-pairs, 2 rows
                    const ulonglong2 av = ae[qn];         // broadcast LDS.128
                    fma2(acc0[2*qn],   av.x, b00);
                    fma2(acc0[2*qn+1], av.y, b00);
                    fma2(acc1[2*qn],   av.x, b10);
                    fma2(acc1[2*qn+1], av.y, b10);
                }
                #pragma unroll
                for (int qn = 0; qn < 8; ++qn){           // odd k
                    const ulonglong2 av = ao[qn];
                    fma2(acc0[2*qn],   av.x, b01);
                    fma2(acc0[2*qn+1], av.y, b01);
                    fma2(acc1[2*qn],   av.x, b11);
                    fma2(acc1[2*qn+1], av.y, b11);
                }
            }
        }
    }

    // ---- write split-K partials: g_partial[c][n][m], m contiguous ----
    float* g0 = g_partial + ((size_t)blockIdx.y * N + n0) * 32;
    float* g1 = g_partial + ((size_t)blockIdx.y * N + n1) * 32;
    #pragma unroll
    for (int i = 0; i < 8; ++i){
        float x0, x1, x2, x3;
        unpack2(acc0[2*i],   x0, x1);
        unpack2(acc0[2*i+1], x2, x3);
        reinterpret_cast<float4*>(g0)[i] = make_float4(x0, x1, x2, x3);
    }
    #pragma unroll
    for (int i = 0; i < 8; ++i){
        float x0, x1, x2, x3;
        unpack2(acc1[2*i],   x0, x1);
        unpack2(acc1[2*i+1], x2, x3);
        reinterpret_cast<float4*>(g1)[i] = make_float4(x0, x1, x2, x3);
    }
}

__global__ void reduce_bias_kernel(
    const float* __restrict__ bias, float* __restrict__ out,
    int N, int M, int KC)
{
    // one thread per (n, 4 tokens)
    int id4 = blockIdx.x * blockDim.x + threadIdx.x;
    int total4 = N * (M >> 2);
    if (id4 >= total4) return;
    int n  = id4 / (M >> 2);
    int m4 = (id4 - n * (M >> 2)) * 4;

    const size_t stride = (size_t)N * M;
    const float* p = g_partial + (size_t)n * M + m4;
    float4 s = make_float4(0.f, 0.f, 0.f, 0.f);
    for (int c = 0; c < KC; ++c){
        float4 v = *reinterpret_cast<const float4*>(p + c * stride);
        s.x += v.x; s.y += v.y; s.z += v.z; s.w += v.w;
    }
    const float b = bias[n];
    out[(size_t)(m4 + 0) * N + n] = s.x + b;
    out[(size_t)(m4 + 1) * N + n] = s.y + b;
    out[(size_t)(m4 + 2) * N + n] = s.z + b;
    out[(size_t)(m4 + 3) * N + n] = s.w + b;
}

extern "C" void kernel_launch(void* const* d_in, const int* in_sizes, int n_in,
                              void* d_out, int out_size)
{
    const float* inp    = (const float*)d_in[0];
    const int*   qw     = (const int*)  d_in[1];
    const float* scales = (const float*)d_in[2];
    const float* amax   = (const float*)d_in[3];
    const float* bias   = (const float*)d_in[4];
    float* out = (float*)d_out;

    const int N = in_sizes[4];
    const int K = (int)(((long long)in_sizes[1] * 2) / N);
    const int M = (int)((long long)in_sizes[0] / K);   // expected 32
    const int KC = K / KTILE;

    dim3 grid(N / 256, KC);
    gemm_fp4_kernel<<<grid, 128>>>(inp, qw, scales, amax, N, K);

    const int total4 = N * (M >> 2);
    reduce_bias_kernel<<<(total4 + 255) / 256, 256>>>(bias, out, N, M, KC);
}